// round 1
// baseline (speedup 1.0000x reference)
#include <cuda_runtime.h>

// MI over 8192x8192 fp32 contingency table, single-pass decomposition:
//   MI = sum_{c>0} c*log2(c) - sum_i mx_i*log2(mx_i) - sum_j my_j*log2(my_j)
// (exact: zero entries contribute 0 to both the masked sum and the marginals)

#define NROWS 8192
#define MCOLS 8192
#define NTHREADS 1024
#define NBLOCKS 148

__device__ float  g_rowsum[NROWS];
__device__ float  g_colsum[MCOLS];
__device__ double g_clogc;

__global__ void mi_zero_kernel() {
    int t = blockIdx.x * blockDim.x + threadIdx.x;
    int stride = gridDim.x * blockDim.x;
    for (int i = t; i < NROWS; i += stride) g_rowsum[i] = 0.0f;
    for (int i = t; i < MCOLS; i += stride) g_colsum[i] = 0.0f;
    if (t == 0) g_clogc = 0.0;
}

__global__ __launch_bounds__(NTHREADS, 1)
void mi_main_kernel(const float* __restrict__ C) {
    const int t = threadIdx.x;

    // Each thread owns 8 fixed columns: {4t..4t+3} and {4096+4t..4096+4t+3}.
    float acc_col0 = 0.f, acc_col1 = 0.f, acc_col2 = 0.f, acc_col3 = 0.f;
    float acc_col4 = 0.f, acc_col5 = 0.f, acc_col6 = 0.f, acc_col7 = 0.f;
    float acc_clogc = 0.f;

    for (int r = blockIdx.x; r < NROWS; r += gridDim.x) {
        const float4* rowp = reinterpret_cast<const float4*>(C + (size_t)r * MCOLS);
        float4 v0 = rowp[t];
        float4 v1 = rowp[t + NTHREADS];

        // row sum contribution
        float rsum = ((v0.x + v0.y) + (v0.z + v0.w)) +
                     ((v1.x + v1.y) + (v1.z + v1.w));

        // column accumulators (fixed column ownership -> registers, no atomics)
        acc_col0 += v0.x; acc_col1 += v0.y; acc_col2 += v0.z; acc_col3 += v0.w;
        acc_col4 += v1.x; acc_col5 += v1.y; acc_col6 += v1.z; acc_col7 += v1.w;

        // sum c*log2(c) over mask c>0  (MUFU.LG2 via __log2f; hidden under HBM)
        float s;
        s  = (v0.x > 0.f) ? v0.x * __log2f(v0.x) : 0.f;
        s += (v0.y > 0.f) ? v0.y * __log2f(v0.y) : 0.f;
        s += (v0.z > 0.f) ? v0.z * __log2f(v0.z) : 0.f;
        s += (v0.w > 0.f) ? v0.w * __log2f(v0.w) : 0.f;
        s += (v1.x > 0.f) ? v1.x * __log2f(v1.x) : 0.f;
        s += (v1.y > 0.f) ? v1.y * __log2f(v1.y) : 0.f;
        s += (v1.z > 0.f) ? v1.z * __log2f(v1.z) : 0.f;
        s += (v1.w > 0.f) ? v1.w * __log2f(v1.w) : 0.f;
        acc_clogc += s;

        // warp-reduce the row sum; one fp32 atomic per warp per row (32/row total)
        #pragma unroll
        for (int off = 16; off > 0; off >>= 1)
            rsum += __shfl_down_sync(0xffffffffu, rsum, off);
        if ((t & 31) == 0)
            atomicAdd(&g_rowsum[r], rsum);
    }

    // flush column accumulators: 148 atomics per column address
    int c0 = 4 * t;
    atomicAdd(&g_colsum[c0 + 0], acc_col0);
    atomicAdd(&g_colsum[c0 + 1], acc_col1);
    atomicAdd(&g_colsum[c0 + 2], acc_col2);
    atomicAdd(&g_colsum[c0 + 3], acc_col3);
    int c1 = 4 * NTHREADS + 4 * t;
    atomicAdd(&g_colsum[c1 + 0], acc_col4);
    atomicAdd(&g_colsum[c1 + 1], acc_col5);
    atomicAdd(&g_colsum[c1 + 2], acc_col6);
    atomicAdd(&g_colsum[c1 + 3], acc_col7);

    // cross-thread reduction of clogc in double
    double d = (double)acc_clogc;
    #pragma unroll
    for (int off = 16; off > 0; off >>= 1)
        d += __shfl_down_sync(0xffffffffu, d, off);
    if ((t & 31) == 0)
        atomicAdd(&g_clogc, d);
}

__global__ __launch_bounds__(NTHREADS)
void mi_final_kernel(float* __restrict__ out) {
    const int t = threadIdx.x;
    double local = 0.0;
    for (int i = t; i < NROWS; i += NTHREADS) {
        double mx = (double)g_rowsum[i];
        if (mx > 0.0) local += mx * log2(mx);
    }
    for (int j = t; j < MCOLS; j += NTHREADS) {
        double my = (double)g_colsum[j];
        if (my > 0.0) local += my * log2(my);
    }

    __shared__ double sh[32];
    #pragma unroll
    for (int off = 16; off > 0; off >>= 1)
        local += __shfl_down_sync(0xffffffffu, local, off);
    if ((t & 31) == 0) sh[t >> 5] = local;
    __syncthreads();
    if (t < 32) {
        double v = (t < (NTHREADS / 32)) ? sh[t] : 0.0;
        #pragma unroll
        for (int off = 16; off > 0; off >>= 1)
            v += __shfl_down_sync(0xffffffffu, v, off);
        if (t == 0)
            out[0] = (float)(g_clogc - v);
    }
}

extern "C" void kernel_launch(void* const* d_in, const int* in_sizes, int n_in,
                              void* d_out, int out_size) {
    const float* C = (const float*)d_in[0];
    float* out = (float*)d_out;

    mi_zero_kernel<<<16, 1024>>>();
    mi_main_kernel<<<NBLOCKS, NTHREADS>>>(C);
    mi_final_kernel<<<1, NTHREADS>>>(out);
}

// round 2
// speedup vs baseline: 1.1444x; 1.1444x over previous
#include <cuda_runtime.h>

// MI over 8192x8192 fp32 contingency table, single-pass decomposition:
//   MI = sum_{c>0} c*log2(c) - sum_i mx_i*log2(mx_i) - sum_j my_j*log2(my_j)
// Round 2: 4-row unroll to raise memory-level parallelism (8 LDG.128 in
// flight per thread -> 32KB/SM), branchless masked c*log2(c) via fmaxf clamp.

#define NROWS 8192
#define MCOLS 8192
#define NTHREADS 1024
#define NBLOCKS 148

__device__ float  g_rowsum[NROWS];
__device__ float  g_colsum[MCOLS];
__device__ double g_clogc;

__global__ void mi_zero_kernel() {
    int t = blockIdx.x * blockDim.x + threadIdx.x;
    int stride = gridDim.x * blockDim.x;
    for (int i = t; i < NROWS; i += stride) g_rowsum[i] = 0.0f;
    for (int i = t; i < MCOLS; i += stride) g_colsum[i] = 0.0f;
    if (t == 0) g_clogc = 0.0;
}

// c*log2(c) with mask c>0, branchless and exact at c==0:
// c==0 -> 0 * log2f(tiny) = 0 * (-99.7) = 0.
__device__ __forceinline__ float clog2c(float v, float& acc) {
    float lg = __log2f(fmaxf(v, 1e-30f));
    return __fmaf_rn(v, lg, acc);
}

__global__ __launch_bounds__(NTHREADS, 1)
void mi_main_kernel(const float* __restrict__ C) {
    const int t = threadIdx.x;

    // Thread-fixed column ownership: columns {4t..4t+3} and {4096+4t..4096+4t+3}.
    float ac0 = 0.f, ac1 = 0.f, ac2 = 0.f, ac3 = 0.f;
    float ac4 = 0.f, ac5 = 0.f, ac6 = 0.f, ac7 = 0.f;
    float acc_clogc = 0.f;

    const int base = blockIdx.x;
    const int cnt = (NROWS - 1 - base) / NBLOCKS + 1;  // rows owned by this block

    int k = 0;
    for (; k + 4 <= cnt; k += 4) {
        const int r0 = base + (k + 0) * NBLOCKS;
        const int r1 = base + (k + 1) * NBLOCKS;
        const int r2 = base + (k + 2) * NBLOCKS;
        const int r3 = base + (k + 3) * NBLOCKS;
        const float4* p0 = reinterpret_cast<const float4*>(C + (size_t)r0 * MCOLS);
        const float4* p1 = reinterpret_cast<const float4*>(C + (size_t)r1 * MCOLS);
        const float4* p2 = reinterpret_cast<const float4*>(C + (size_t)r2 * MCOLS);
        const float4* p3 = reinterpret_cast<const float4*>(C + (size_t)r3 * MCOLS);

        // Front-batched independent loads: 8 LDG.128 in flight per thread.
        float4 a0 = p0[t], a1 = p0[t + NTHREADS];
        float4 b0 = p1[t], b1 = p1[t + NTHREADS];
        float4 c0 = p2[t], c1 = p2[t + NTHREADS];
        float4 d0 = p3[t], d1 = p3[t + NTHREADS];

        // Row sums (4 independent values per thread).
        float rs0 = ((a0.x + a0.y) + (a0.z + a0.w)) + ((a1.x + a1.y) + (a1.z + a1.w));
        float rs1 = ((b0.x + b0.y) + (b0.z + b0.w)) + ((b1.x + b1.y) + (b1.z + b1.w));
        float rs2 = ((c0.x + c0.y) + (c0.z + c0.w)) + ((c1.x + c1.y) + (c1.z + c1.w));
        float rs3 = ((d0.x + d0.y) + (d0.z + d0.w)) + ((d1.x + d1.y) + (d1.z + d1.w));

        // Column accumulators (tree-add 4 rows first).
        ac0 += (a0.x + b0.x) + (c0.x + d0.x);
        ac1 += (a0.y + b0.y) + (c0.y + d0.y);
        ac2 += (a0.z + b0.z) + (c0.z + d0.z);
        ac3 += (a0.w + b0.w) + (c0.w + d0.w);
        ac4 += (a1.x + b1.x) + (c1.x + d1.x);
        ac5 += (a1.y + b1.y) + (c1.y + d1.y);
        ac6 += (a1.z + b1.z) + (c1.z + d1.z);
        ac7 += (a1.w + b1.w) + (c1.w + d1.w);

        // sum c*log2(c): 32 MUFU + 32 FFMA, no predication.
        acc_clogc = clog2c(a0.x, acc_clogc); acc_clogc = clog2c(a0.y, acc_clogc);
        acc_clogc = clog2c(a0.z, acc_clogc); acc_clogc = clog2c(a0.w, acc_clogc);
        acc_clogc = clog2c(a1.x, acc_clogc); acc_clogc = clog2c(a1.y, acc_clogc);
        acc_clogc = clog2c(a1.z, acc_clogc); acc_clogc = clog2c(a1.w, acc_clogc);
        acc_clogc = clog2c(b0.x, acc_clogc); acc_clogc = clog2c(b0.y, acc_clogc);
        acc_clogc = clog2c(b0.z, acc_clogc); acc_clogc = clog2c(b0.w, acc_clogc);
        acc_clogc = clog2c(b1.x, acc_clogc); acc_clogc = clog2c(b1.y, acc_clogc);
        acc_clogc = clog2c(b1.z, acc_clogc); acc_clogc = clog2c(b1.w, acc_clogc);
        acc_clogc = clog2c(c0.x, acc_clogc); acc_clogc = clog2c(c0.y, acc_clogc);
        acc_clogc = clog2c(c0.z, acc_clogc); acc_clogc = clog2c(c0.w, acc_clogc);
        acc_clogc = clog2c(c1.x, acc_clogc); acc_clogc = clog2c(c1.y, acc_clogc);
        acc_clogc = clog2c(c1.z, acc_clogc); acc_clogc = clog2c(c1.w, acc_clogc);
        acc_clogc = clog2c(d0.x, acc_clogc); acc_clogc = clog2c(d0.y, acc_clogc);
        acc_clogc = clog2c(d0.z, acc_clogc); acc_clogc = clog2c(d0.w, acc_clogc);
        acc_clogc = clog2c(d1.x, acc_clogc); acc_clogc = clog2c(d1.y, acc_clogc);
        acc_clogc = clog2c(d1.z, acc_clogc); acc_clogc = clog2c(d1.w, acc_clogc);

        // 4 independent shuffle-reduction chains (interleave in the scheduler).
        #pragma unroll
        for (int off = 16; off > 0; off >>= 1) {
            rs0 += __shfl_down_sync(0xffffffffu, rs0, off);
            rs1 += __shfl_down_sync(0xffffffffu, rs1, off);
            rs2 += __shfl_down_sync(0xffffffffu, rs2, off);
            rs3 += __shfl_down_sync(0xffffffffu, rs3, off);
        }
        if ((t & 31) == 0) {
            atomicAdd(&g_rowsum[r0], rs0);
            atomicAdd(&g_rowsum[r1], rs1);
            atomicAdd(&g_rowsum[r2], rs2);
            atomicAdd(&g_rowsum[r3], rs3);
        }
    }

    // Tail rows (0..3 of them).
    for (; k < cnt; ++k) {
        const int r = base + k * NBLOCKS;
        const float4* p = reinterpret_cast<const float4*>(C + (size_t)r * MCOLS);
        float4 v0 = p[t], v1 = p[t + NTHREADS];

        float rs = ((v0.x + v0.y) + (v0.z + v0.w)) + ((v1.x + v1.y) + (v1.z + v1.w));

        ac0 += v0.x; ac1 += v0.y; ac2 += v0.z; ac3 += v0.w;
        ac4 += v1.x; ac5 += v1.y; ac6 += v1.z; ac7 += v1.w;

        acc_clogc = clog2c(v0.x, acc_clogc); acc_clogc = clog2c(v0.y, acc_clogc);
        acc_clogc = clog2c(v0.z, acc_clogc); acc_clogc = clog2c(v0.w, acc_clogc);
        acc_clogc = clog2c(v1.x, acc_clogc); acc_clogc = clog2c(v1.y, acc_clogc);
        acc_clogc = clog2c(v1.z, acc_clogc); acc_clogc = clog2c(v1.w, acc_clogc);

        #pragma unroll
        for (int off = 16; off > 0; off >>= 1)
            rs += __shfl_down_sync(0xffffffffu, rs, off);
        if ((t & 31) == 0)
            atomicAdd(&g_rowsum[r], rs);
    }

    // Flush column accumulators: 148 atomics per column address.
    int cA = 4 * t;
    atomicAdd(&g_colsum[cA + 0], ac0);
    atomicAdd(&g_colsum[cA + 1], ac1);
    atomicAdd(&g_colsum[cA + 2], ac2);
    atomicAdd(&g_colsum[cA + 3], ac3);
    int cB = 4 * NTHREADS + 4 * t;
    atomicAdd(&g_colsum[cB + 0], ac4);
    atomicAdd(&g_colsum[cB + 1], ac5);
    atomicAdd(&g_colsum[cB + 2], ac6);
    atomicAdd(&g_colsum[cB + 3], ac7);

    // Cross-thread reduction of clogc in double.
    double d = (double)acc_clogc;
    #pragma unroll
    for (int off = 16; off > 0; off >>= 1)
        d += __shfl_down_sync(0xffffffffu, d, off);
    if ((t & 31) == 0)
        atomicAdd(&g_clogc, d);
}

__global__ __launch_bounds__(NTHREADS)
void mi_final_kernel(float* __restrict__ out) {
    const int t = threadIdx.x;
    double local = 0.0;
    for (int i = t; i < NROWS; i += NTHREADS) {
        double mx = (double)g_rowsum[i];
        if (mx > 0.0) local += mx * log2(mx);
    }
    for (int j = t; j < MCOLS; j += NTHREADS) {
        double my = (double)g_colsum[j];
        if (my > 0.0) local += my * log2(my);
    }

    __shared__ double sh[32];
    #pragma unroll
    for (int off = 16; off > 0; off >>= 1)
        local += __shfl_down_sync(0xffffffffu, local, off);
    if ((t & 31) == 0) sh[t >> 5] = local;
    __syncthreads();
    if (t < 32) {
        double v = (t < (NTHREADS / 32)) ? sh[t] : 0.0;
        #pragma unroll
        for (int off = 16; off > 0; off >>= 1)
            v += __shfl_down_sync(0xffffffffu, v, off);
        if (t == 0)
            out[0] = (float)(g_clogc - v);
    }
}

extern "C" void kernel_launch(void* const* d_in, const int* in_sizes, int n_in,
                              void* d_out, int out_size) {
    const float* C = (const float*)d_in[0];
    float* out = (float*)d_out;

    mi_zero_kernel<<<16, 1024>>>();
    mi_main_kernel<<<NBLOCKS, NTHREADS>>>(C);
    mi_final_kernel<<<1, NTHREADS>>>(out);
}